// round 6
// baseline (speedup 1.0000x reference)
#include <cuda_runtime.h>
#include <math.h>

#define B_ 64
#define W_ 256
#define N_ 128
#define L_ 64
#define WC 128          // windows per block (2 blocks per batch)
#define THREADS 512
#define PADX 260        // sx_dup row: 256 dup'd floats + 4 pad (16B-aligned steps)
#define PADS 132        // ss row: 128 floats + 4 pad

// Per-(b, half) min d^2 slices + arrival counter (zero at load; reset each call).
__device__ float g_part[B_][2][N_];
__device__ int   g_cnt[B_];

#define FMA_F32X2(d, a, b, c) \
    asm("fma.rn.f32x2 %0, %1, %2, %3;" : "=l"(d) : "l"(a), "l"(b), "l"(c))

__global__ void __launch_bounds__(THREADS) fused_kernel(const float* __restrict__ x,
                                                        const float* __restrict__ sh,
                                                        const float* __restrict__ cw,
                                                        const float* __restrict__ cb,
                                                        float* __restrict__ out) {
    extern __shared__ float smem[];
    float* sx  = smem;                        // [L_][PADX] windows dup'd, k-major, value = -2x
    float* ss  = sx + L_ * PADX;              // [L_][PADS] shapelets, k-major
    float* sxx = ss + L_ * PADS;              // [WC]  window norms (sum x^2)
    float* ssn = sxx + WC;                    // [N_]  shapelet norms
    unsigned int* umin = (unsigned int*)(ssn + N_);   // [N_] block-local min d^2 bits
    float* red = (float*)(umin + N_);         // [4]
    int*  tkt  = (int*)(red + 4);             // [1]

    const int b    = blockIdx.x >> 1;
    const int half = blockIdx.x & 1;
    const int tid  = threadIdx.x;

    const float* xb = x + (size_t)(b * W_ + half * WC) * L_;

    // ---- load: x -> dup'd k-major scaled by -2 ; sh -> k-major ----
    for (int i = tid; i < WC * L_; i += THREADS) {
        int w = i >> 6, k = i & 63;
        float v = -2.f * xb[i];
        *(float2*)(sx + k * PADX + 2 * w) = make_float2(v, v);
    }
    for (int i = tid; i < N_ * L_; i += THREADS) {
        int n = i >> 6, k = i & 63;
        ss[k * PADS + n] = sh[i];
    }
    if (tid < N_) umin[tid] = 0x7F800000u;
    __syncthreads();

    // ---- norms (threads 0-127: windows; 128-255: shapelets) ----
    if (tid < WC) {
        float s = 0.f;
        #pragma unroll
        for (int k = 0; k < L_; k++) { float v = sx[k * PADX + 2 * tid]; s = fmaf(v, v, s); }
        sxx[tid] = 0.25f * s;                 // undo the -2 factor
    } else if (tid < WC + N_) {
        int n = tid - WC;
        float s = 0.f;
        #pragma unroll
        for (int k = 0; k < L_; k++) { float v = ss[k * PADS + n]; s = fmaf(v, v, s); }
        ssn[n] = s;
    }
    __syncthreads();

    // ---- 128x128x64 tile: thread = 4 windows x 8 shapelets, packed f32x2 ----
    const int tx = tid & 15;                  // shapelets 8*tx .. 8*tx+7
    const int ty = tid >> 4;                  // windows   4*ty .. 4*ty+3

    unsigned long long acc[4][4];             // [window m][shapelet pair p]
    #pragma unroll
    for (int m = 0; m < 4; m++)
        #pragma unroll
        for (int p = 0; p < 4; p++) acc[m][p] = 0ull;

    const float* ax = sx + 8 * ty;            // dup'd window quad base
    const float* cs = ss + 8 * tx;            // shapelet octet base

    #pragma unroll 4
    for (int k = 0; k < L_; k++) {
        ulonglong2 av0 = *(const ulonglong2*)(ax + k * PADX);      // (w0,w0),(w1,w1)
        ulonglong2 av1 = *(const ulonglong2*)(ax + k * PADX + 4);  // (w2,w2),(w3,w3)
        ulonglong2 cv0 = *(const ulonglong2*)(cs + k * PADS);      // (s0,s1),(s2,s3)
        ulonglong2 cv1 = *(const ulonglong2*)(cs + k * PADS + 4);  // (s4,s5),(s6,s7)
        unsigned long long a[4] = {av0.x, av0.y, av1.x, av1.y};
        unsigned long long c[4] = {cv0.x, cv0.y, cv1.x, cv1.y};
        #pragma unroll
        for (int m = 0; m < 4; m++)
            #pragma unroll
            for (int p = 0; p < 4; p++)
                FMA_F32X2(acc[m][p], a[m], c[p], acc[m][p]);
    }

    // ---- d^2 = xx + sn + acc (acc already = -2*dot); min over 4 windows ----
    float xx[4];
    #pragma unroll
    for (int m = 0; m < 4; m++) xx[m] = sxx[4 * ty + m];

    #pragma unroll
    for (int p = 0; p < 4; p++) {
        int n0 = 8 * tx + 2 * p;
        float s0 = ssn[n0], s1 = ssn[n0 + 1];
        float mn0 = 3.402823466e+38f, mn1 = 3.402823466e+38f;
        #pragma unroll
        for (int m = 0; m < 4; m++) {
            float lo = __uint_as_float((unsigned int)acc[m][p]);
            float hi = __uint_as_float((unsigned int)(acc[m][p] >> 32));
            mn0 = fminf(mn0, xx[m] + s0 + lo);
            mn1 = fminf(mn1, xx[m] + s1 + hi);
        }
        atomicMin(&umin[n0],     __float_as_uint(fmaxf(mn0, 0.f)));
        atomicMin(&umin[n0 + 1], __float_as_uint(fmaxf(mn1, 0.f)));
    }
    __syncthreads();

    // ---- publish own half, draw ticket; last block merges + classifies ----
    if (tid < N_) __stcg(&g_part[b][half][tid], __uint_as_float(umin[tid]));
    __threadfence();
    __syncthreads();
    if (tid == 0) tkt[0] = atomicAdd(&g_cnt[b], 1);
    __syncthreads();

    if (tkt[0] == 1) {
        __threadfence();
        float v = 0.f;
        if (tid < N_) {
            float other = __ldcg(&g_part[b][1 - half][tid]);
            float d2 = fminf(__uint_as_float(umin[tid]), other);
            v = sqrtf(fmaxf(d2, 0.f)) * cw[tid];
        }
        #pragma unroll
        for (int o = 16; o; o >>= 1) v += __shfl_xor_sync(0xffffffffu, v, o);
        if (tid < N_ && (tid & 31) == 0) red[tid >> 5] = v;
        __syncthreads();
        if (tid == 0) {
            float s = red[0] + red[1] + red[2] + red[3] + cb[0];
            out[b] = 1.f / (1.f + expf(-s));
            atomicExch(&g_cnt[b], 0);          // reset for next graph replay
        }
    }
}

extern "C" void kernel_launch(void* const* d_in, const int* in_sizes, int n_in,
                              void* d_out, int out_size) {
    const float* x    = (const float*)d_in[0];
    const float* sh   = (const float*)d_in[1];
    const float* cw   = (const float*)d_in[2];
    const float* cb   = (const float*)d_in[3];
    float* out = (float*)d_out;

    const int smem_bytes = (L_ * PADX + L_ * PADS + WC + N_ + N_ + 4 + 4) * 4;
    cudaFuncSetAttribute(fused_kernel, cudaFuncAttributeMaxDynamicSharedMemorySize, smem_bytes);

    fused_kernel<<<2 * B_, THREADS, smem_bytes>>>(x, sh, cw, cb, out);
}

// round 8
// speedup vs baseline: 1.9750x; 1.9750x over previous
#include <cuda_runtime.h>
#include <cuda_bf16.h>
#include <stdint.h>
#include <math.h>

#define B_ 64
#define W_ 256
#define N_ 128
#define L_ 64
#define WC 128
#define THREADS 256
#define PADK 72                    // bf16 row stride: 144B -> conflict-free ldmatrix

// smem byte offsets
#define OFF_AHI 0
#define OFF_ALO 18432
#define OFF_BHI 36864
#define OFF_BLO 55296
#define OFF_SXX 73728              // [128] f32 window norms
#define OFF_SSN (73728 + 512)      // [128] f32 shapelet norms
#define OFF_UMIN (73728 + 1024)    // [128] u32 min d^2 bits
#define OFF_RED (73728 + 1536)     // [4] f32
#define OFF_TKT (73728 + 1552)     // [1] int
#define SMEM_TOTAL (73728 + 1600)

__device__ float g_part[B_][2][N_];
__device__ int   g_cnt[B_];

__device__ __forceinline__ uint32_t smem_u32(const void* p) {
    uint32_t a;
    asm("{ .reg .u64 t; cvta.to.shared.u64 t, %1; cvt.u32.u64 %0, t; }" : "=r"(a) : "l"(p));
    return a;
}

#define LDSM_X4(r, addr) \
    asm volatile("ldmatrix.sync.aligned.m8n8.x4.shared.b16 {%0,%1,%2,%3}, [%4];" \
                 : "=r"((r)[0]), "=r"((r)[1]), "=r"((r)[2]), "=r"((r)[3]) : "r"(addr))

#define MMA_BF16(c, a, b0, b1) \
    asm volatile("mma.sync.aligned.m16n8k16.row.col.f32.bf16.bf16.f32 " \
                 "{%0,%1,%2,%3},{%4,%5,%6,%7},{%8,%9},{%0,%1,%2,%3};" \
                 : "+f"((c)[0]), "+f"((c)[1]), "+f"((c)[2]), "+f"((c)[3]) \
                 : "r"((a)[0]), "r"((a)[1]), "r"((a)[2]), "r"((a)[3]), "r"(b0), "r"(b1))

__global__ void __launch_bounds__(THREADS) fused_kernel(const float* __restrict__ x,
                                                        const float* __restrict__ sh,
                                                        const float* __restrict__ cw,
                                                        const float* __restrict__ cb,
                                                        float* __restrict__ out) {
    extern __shared__ char sm[];
    const uint32_t smb = smem_u32(sm);
    const int tid  = threadIdx.x;
    const int wid  = tid >> 5, lane = tid & 31;
    const int b    = blockIdx.x >> 1, half = blockIdx.x & 1;

    float* sxx = (float*)(sm + OFF_SXX);
    float* ssn = (float*)(sm + OFF_SSN);
    unsigned int* umin = (unsigned int*)(sm + OFF_UMIN);
    float* red = (float*)(sm + OFF_RED);
    int*   tkt = (int*)(sm + OFF_TKT);

    if (tid < N_) umin[tid] = 0x7F800000u;

    // ---- phase 1: load fp32, split into (hi, lo) bf16 tiles, fp32 row norms ----
    // Each warp-iteration covers exactly one row (32 lanes x float2 = 64 elems),
    // so the row norm falls out of a warp reduction for free.
    {
        const float* xb = x + (size_t)(b * W_ + half * WC) * L_;
        #pragma unroll
        for (int it = 0; it < 16; it++) {
            int row = wid + it * 8;
            float2 v = *(const float2*)(xb + row * L_ + lane * 2);
            __nv_bfloat16 h0 = __float2bfloat16_rn(v.x), h1 = __float2bfloat16_rn(v.y);
            __nv_bfloat162 hp; hp.x = h0; hp.y = h1;
            __nv_bfloat162 lp;
            lp.x = __float2bfloat16_rn(v.x - __bfloat162float(h0));
            lp.y = __float2bfloat16_rn(v.y - __bfloat162float(h1));
            uint32_t o = (uint32_t)(row * PADK + lane * 2) * 2;
            *(__nv_bfloat162*)(sm + OFF_AHI + o) = hp;
            *(__nv_bfloat162*)(sm + OFF_ALO + o) = lp;
            float nr = fmaf(v.x, v.x, v.y * v.y);
            #pragma unroll
            for (int of = 16; of; of >>= 1) nr += __shfl_xor_sync(0xffffffffu, nr, of);
            if (lane == 0) sxx[row] = nr;
        }
        #pragma unroll
        for (int it = 0; it < 16; it++) {
            int row = wid + it * 8;
            float2 v = *(const float2*)(sh + row * L_ + lane * 2);
            __nv_bfloat16 h0 = __float2bfloat16_rn(v.x), h1 = __float2bfloat16_rn(v.y);
            __nv_bfloat162 hp; hp.x = h0; hp.y = h1;
            __nv_bfloat162 lp;
            lp.x = __float2bfloat16_rn(v.x - __bfloat162float(h0));
            lp.y = __float2bfloat16_rn(v.y - __bfloat162float(h1));
            uint32_t o = (uint32_t)(row * PADK + lane * 2) * 2;
            *(__nv_bfloat162*)(sm + OFF_BHI + o) = hp;
            *(__nv_bfloat162*)(sm + OFF_BLO + o) = lp;
            float nr = fmaf(v.x, v.x, v.y * v.y);
            #pragma unroll
            for (int of = 16; of; of >>= 1) nr += __shfl_xor_sync(0xffffffffu, nr, of);
            if (lane == 0) ssn[row] = nr;
        }
    }
    __syncthreads();

    // ---- phase 2: warp-tiled mma: warp = 32(M) x 64(N), K = 3 passes x 64 ----
    const int mbase = (wid & 3) * 32;
    const int nbase = (wid >> 2) * 64;

    float acc[2][8][4];
    #pragma unroll
    for (int mt = 0; mt < 2; mt++)
        #pragma unroll
        for (int j = 0; j < 8; j++)
            #pragma unroll
            for (int e = 0; e < 4; e++) acc[mt][j][e] = 0.f;

    // per-lane ldmatrix addresses
    const uint32_t a_off = (uint32_t)((mbase + (lane & 15)) * PADK + (lane >> 4) * 8) * 2;
    const uint32_t q = lane >> 3;
    const uint32_t b_off = (uint32_t)((nbase + ((q >> 1) << 3) + (lane & 7)) * PADK
                                      + (q & 1) * 8) * 2;

    const uint32_t aB[3] = {smb + OFF_AHI + a_off, smb + OFF_AHI + a_off, smb + OFF_ALO + a_off};
    const uint32_t bB[3] = {smb + OFF_BHI + b_off, smb + OFF_BLO + b_off, smb + OFF_BHI + b_off};

    #pragma unroll
    for (int p = 0; p < 3; p++) {
        #pragma unroll
        for (int ks = 0; ks < 4; ks++) {
            const uint32_t ko = ks * 32;     // 16 bf16 cols = 32 bytes
            uint32_t A0[4], A1[4], Bf[4][4];
            LDSM_X4(A0, aB[p] + ko);
            LDSM_X4(A1, aB[p] + 16 * PADK * 2 + ko);
            #pragma unroll
            for (int jp = 0; jp < 4; jp++)
                LDSM_X4(Bf[jp], bB[p] + jp * 16 * PADK * 2 + ko);
            #pragma unroll
            for (int mt = 0; mt < 2; mt++)
                #pragma unroll
                for (int j = 0; j < 8; j++)
                    MMA_BF16(acc[mt][j], (mt ? A1 : A0),
                             Bf[j >> 1][(j & 1) * 2], Bf[j >> 1][(j & 1) * 2 + 1]);
        }
    }

    // ---- epilogue: d^2 = xr + sn - 2*dot; min over rows (frag rows + groups) ----
    {
        const int g = lane >> 2, t = lane & 3;
        const float xr0 = sxx[mbase + g],      xr1 = sxx[mbase + 8 + g];
        const float xr2 = sxx[mbase + 16 + g], xr3 = sxx[mbase + 24 + g];
        #pragma unroll
        for (int j = 0; j < 8; j++) {
            float v0 = fminf(fminf(fmaf(-2.f, acc[0][j][0], xr0), fmaf(-2.f, acc[0][j][2], xr1)),
                             fminf(fmaf(-2.f, acc[1][j][0], xr2), fmaf(-2.f, acc[1][j][2], xr3)));
            float v1 = fminf(fminf(fmaf(-2.f, acc[0][j][1], xr0), fmaf(-2.f, acc[0][j][3], xr1)),
                             fminf(fmaf(-2.f, acc[1][j][1], xr2), fmaf(-2.f, acc[1][j][3], xr3)));
            #pragma unroll
            for (int o = 4; o <= 16; o <<= 1) {
                v0 = fminf(v0, __shfl_xor_sync(0xffffffffu, v0, o));
                v1 = fminf(v1, __shfl_xor_sync(0xffffffffu, v1, o));
            }
            if (lane < 4) {
                int c0 = nbase + j * 8 + t * 2;
                atomicMin(&umin[c0],     __float_as_uint(fmaxf(v0 + ssn[c0], 0.f)));
                atomicMin(&umin[c0 + 1], __float_as_uint(fmaxf(v1 + ssn[c0 + 1], 0.f)));
            }
        }
    }
    __syncthreads();

    // ---- publish half-min, ticket; last block of the pair merges + classifies ----
    if (tid < N_) __stcg(&g_part[b][half][tid], __uint_as_float(umin[tid]));
    __threadfence();
    __syncthreads();
    if (tid == 0) tkt[0] = atomicAdd(&g_cnt[b], 1);
    __syncthreads();

    if (tkt[0] == 1) {
        __threadfence();
        float v = 0.f;
        if (tid < N_) {
            float other = __ldcg(&g_part[b][1 - half][tid]);
            float d2 = fminf(__uint_as_float(umin[tid]), other);
            v = sqrtf(fmaxf(d2, 0.f)) * cw[tid];
        }
        #pragma unroll
        for (int o = 16; o; o >>= 1) v += __shfl_xor_sync(0xffffffffu, v, o);
        if (tid < N_ && (tid & 31) == 0) red[tid >> 5] = v;
        __syncthreads();
        if (tid == 0) {
            float s = red[0] + red[1] + red[2] + red[3] + cb[0];
            out[b] = 1.f / (1.f + expf(-s));
            atomicExch(&g_cnt[b], 0);          // reset for next graph replay
        }
    }
}

extern "C" void kernel_launch(void* const* d_in, const int* in_sizes, int n_in,
                              void* d_out, int out_size) {
    const float* x  = (const float*)d_in[0];
    const float* sh = (const float*)d_in[1];
    const float* cw = (const float*)d_in[2];
    const float* cb = (const float*)d_in[3];
    float* out = (float*)d_out;

    cudaFuncSetAttribute(fused_kernel, cudaFuncAttributeMaxDynamicSharedMemorySize, SMEM_TOTAL);
    fused_kernel<<<2 * B_, THREADS, SMEM_TOTAL>>>(x, sh, cw, cb, out);
}